// round 13
// baseline (speedup 1.0000x reference)
#include <cuda_runtime.h>

// Fused: conv3d(16->32, k3, pad1) + bias + maxpool(2x2x2) + logsumexp(ch) + relu
// x: (16,16,32,64,64) f32, w: (32,16,3,3,3) f32, bias: (32) f32
// out: (16,1,16,32,32) f32
//
// R12 (post-mortem R11 win, fma=60.5%: remaining gap = LDS latency exposure at
// 4 warps/SMSP):
//  - Weights moved OUT of smem: pre-kernel rearranges w into a __device__ global
//    buffer, 16B entry per (ic,tap,g) = {w[g], w[g+16], w[g+8], w[g+24]}.
//    Main kernel LDG.128: lanes g=0..7 hit one 128B line; 55KB stays L1-resident.
//  - smem = x tile only (46 KB) -> 3 blocks/SM (6 warps/SMSP), launch_bounds(256,3).
//  - x rows loaded as aligned float2 (halves x LDS issue count).

#define TOH 4
#define TOW 8
#define SMEM_X_FLOATS (16 * 4 * 10 * 18)         // 11520 floats = 46080 B
#define SMEM_BYTES    (SMEM_X_FLOATS * 4)

typedef unsigned long long ull;

__device__ __align__(16) float g_wre[13824];     // rearranged weights (55.3 KB)

__device__ __forceinline__ ull pack2(float v) {
    unsigned r = __float_as_uint(v);
    ull d;
    asm("mov.b64 %0, {%1, %1};" : "=l"(d) : "r"(r));
    return d;
}

__device__ __forceinline__ void fma2(ull& a, ull b, ull c) {
    // packed dual-fp32 FMA (Blackwell f32x2 pipe)
    asm("fma.rn.f32x2 %0, %1, %2, %3;" : "=l"(a) : "l"(b), "l"(c), "l"(a));
}

__global__ void rearrange_w_kernel(const float* __restrict__ w) {
    int j = blockIdx.x * 256 + threadIdx.x;
    if (j < 13824) {
        int ic  = j / 864;
        int r   = j - ic * 864;
        int tap = r >> 5;
        int q   = r & 31;
        int g   = q >> 2;
        int s   = q & 3;
        int oc  = g + ((s & 1) << 4) + ((s >> 1) << 3);
        g_wre[j] = w[oc * 432 + ic * 27 + tap];
    }
}

__global__ __launch_bounds__(256, 3)
void conv_pool_lse_kernel(const float* __restrict__ x,
                          const float* __restrict__ bias,
                          float* __restrict__ out) {
    extern __shared__ char smem[];
    float* xs = reinterpret_cast<float*>(smem);                 // [16][4][10][18]

    const int tid = threadIdx.x;
    const int bz = blockIdx.z;
    const int b  = bz >> 4;
    const int od = bz & 15;
    const int OH0 = blockIdx.y * TOH;
    const int OW0 = blockIdx.x * TOW;

    // ---- x tile (halo + zero pad): xs[ic][xd][xh][xw], 4x10x18 per ic ----
    {
        const int d0 = od * 2 - 1;
        const int h0 = OH0 * 2 - 1;
        const int w0 = OW0 * 2 - 1;
        const float* xb = x + (long)b * (16 * 32 * 64 * 64);
        for (int i = tid; i < SMEM_X_FLOATS; i += 256) {
            int ic = i / 720;
            int r  = i - ic * 720;
            int xd = r / 180; r -= xd * 180;
            int xh = r / 18;
            int xw = r - xh * 18;
            int gd = d0 + xd, gh = h0 + xh, gw = w0 + xw;
            float v = 0.0f;
            if ((unsigned)gd < 32u && (unsigned)gh < 64u && (unsigned)gw < 64u)
                v = xb[((ic * 32 + gd) * 64 + gh) * 64 + gw];
            xs[i] = v;
        }
    }
    __syncthreads();

    // ---- main compute ----
    const int g   = tid & 7;           // oc group: channels g, g+16 (A) and g+8, g+24 (B)
    const int pos = tid >> 3;          // 0..31 pooled positions
    const int ph  = pos >> 3;          // 0..3
    const int pw  = pos & 7;           // 0..7
    const int ch  = ph * 2;            // conv-row base within tile (0..6)
    const int cw  = pw * 2;

    ull accA[2][2][2], accB[2][2][2];
#pragma unroll
    for (int i = 0; i < 2; ++i)
#pragma unroll
        for (int j = 0; j < 2; ++j)
#pragma unroll
            for (int k = 0; k < 2; ++k) { accA[i][j][k] = 0ull; accB[i][j][k] = 0ull; }

#pragma unroll 1
    for (int ic = 0; ic < 16; ++ic) {
        const float* xsl = xs + ic * 720;
        const ulonglong2* wl =
            reinterpret_cast<const ulonglong2*>(g_wre) + ic * (27 * 8) + g;

#pragma unroll
        for (int xd = 0; xd < 4; ++xd) {
            // 4x4 patch at depth slice xd; rows loaded as aligned float2 pairs,
            // then duplicated to f32x2 operands.
            ull xp[16];
#pragma unroll
            for (int row = 0; row < 4; ++row) {
                const float* rp = xsl + xd * 180 + (ch + row) * 18 + cw;
                float2 p0 = *reinterpret_cast<const float2*>(rp);
                float2 p1 = *reinterpret_cast<const float2*>(rp + 2);
                xp[row * 4 + 0] = pack2(p0.x);
                xp[row * 4 + 1] = pack2(p0.y);
                xp[row * 4 + 2] = pack2(p1.x);
                xp[row * 4 + 3] = pack2(p1.y);
            }

#pragma unroll
            for (int dd = 0; dd < 2; ++dd) {
                const int kd = xd - dd;
                if (kd < 0 || kd > 2) continue;
#pragma unroll
                for (int kh = 0; kh < 3; ++kh) {
                    // one LDG.128 per tap (128B line per warp, L1-resident)
                    ulonglong2 w0 = wl[(kd * 9 + kh * 3 + 0) * 8];
                    ulonglong2 w1 = wl[(kd * 9 + kh * 3 + 1) * 8];
                    ulonglong2 w2 = wl[(kd * 9 + kh * 3 + 2) * 8];
#pragma unroll
                    for (int kw = 0; kw < 3; ++kw) {
                        ulonglong2 wq = (kw == 0) ? w0 : (kw == 1) ? w1 : w2;
                        ull x00 = xp[(kh + 0) * 4 + kw + 0];
                        ull x01 = xp[(kh + 0) * 4 + kw + 1];
                        ull x10 = xp[(kh + 1) * 4 + kw + 0];
                        ull x11 = xp[(kh + 1) * 4 + kw + 1];
                        fma2(accA[dd][0][0], wq.x, x00);
                        fma2(accA[dd][0][1], wq.x, x01);
                        fma2(accA[dd][1][0], wq.x, x10);
                        fma2(accA[dd][1][1], wq.x, x11);
                        fma2(accB[dd][0][0], wq.y, x00);
                        fma2(accB[dd][0][1], wq.y, x01);
                        fma2(accB[dd][1][0], wq.y, x10);
                        fma2(accB[dd][1][1], wq.y, x11);
                    }
                }
            }
        }
    }

    // ---- maxpool over the 2x2x2 accumulators, + bias (4 channels/thread) ----
    float mA0 = -3.0e38f, mA1 = -3.0e38f, mB0 = -3.0e38f, mB1 = -3.0e38f;
#pragma unroll
    for (int i = 0; i < 2; ++i)
#pragma unroll
        for (int j = 0; j < 2; ++j)
#pragma unroll
            for (int k = 0; k < 2; ++k) {
                ull a = accA[i][j][k];
                ull c = accB[i][j][k];
                mA0 = fmaxf(mA0, __uint_as_float((unsigned)a));
                mA1 = fmaxf(mA1, __uint_as_float((unsigned)(a >> 32)));
                mB0 = fmaxf(mB0, __uint_as_float((unsigned)c));
                mB1 = fmaxf(mB1, __uint_as_float((unsigned)(c >> 32)));
            }
    mA0 += bias[g];
    mA1 += bias[g + 16];
    mB0 += bias[g + 8];
    mB1 += bias[g + 24];

    // ---- logsumexp over 32 channels (8 lanes x 4 channels each) + relu ----
    float m = fmaxf(fmaxf(mA0, mA1), fmaxf(mB0, mB1));
#pragma unroll
    for (int msk = 4; msk; msk >>= 1)
        m = fmaxf(m, __shfl_xor_sync(0xffffffffu, m, msk));
    float s = expf(mA0 - m) + expf(mA1 - m) + expf(mB0 - m) + expf(mB1 - m);
#pragma unroll
    for (int msk = 4; msk; msk >>= 1)
        s += __shfl_xor_sync(0xffffffffu, s, msk);

    if (g == 0) {
        float r = m + logf(s);
        out[((b * 16 + od) * 32 + (OH0 + ph)) * 32 + (OW0 + pw)] = fmaxf(r, 0.0f);
    }
}

extern "C" void kernel_launch(void* const* d_in, const int* in_sizes, int n_in,
                              void* d_out, int out_size) {
    (void)in_sizes; (void)n_in; (void)out_size;
    const float* x    = (const float*)d_in[0];
    const float* w    = (const float*)d_in[1];
    const float* bias = (const float*)d_in[2];
    float* out        = (float*)d_out;

    // 1) rearrange weights into the LDG-friendly interleaved layout
    rearrange_w_kernel<<<54, 256>>>(w);

    // 2) fused conv+pool+lse kernel (x tile in smem; weights via L1-cached LDG)
    dim3 grid(32 / TOW, 32 / TOH, 16 * 16);   // (4 ow tiles, 8 oh tiles, b*od)
    conv_pool_lse_kernel<<<grid, 256, SMEM_BYTES>>>(x, bias, out);
}

// round 14
// speedup vs baseline: 1.0005x; 1.0005x over previous
#include <cuda_runtime.h>

// Fused: conv3d(16->32, k3, pad1) + bias + maxpool(2x2x2) + logsumexp(ch) + relu
// x: (16,16,32,64,64) f32, w: (32,16,3,3,3) f32, bias: (32) f32
// out: (16,1,16,32,32) f32
//
// R12 (post-mortem R11 win, fma=60.5%: remaining gap = LDS latency exposure at
// 4 warps/SMSP):
//  - Weights moved OUT of smem: pre-kernel rearranges w into a __device__ global
//    buffer, 16B entry per (ic,tap,g) = {w[g], w[g+16], w[g+8], w[g+24]}.
//    Main kernel LDG.128: lanes g=0..7 hit one 128B line; 55KB stays L1-resident.
//  - smem = x tile only (46 KB) -> 3 blocks/SM (6 warps/SMSP), launch_bounds(256,3).
//  - x rows loaded as aligned float2 (halves x LDS issue count).

#define TOH 4
#define TOW 8
#define SMEM_X_FLOATS (16 * 4 * 10 * 18)         // 11520 floats = 46080 B
#define SMEM_BYTES    (SMEM_X_FLOATS * 4)

typedef unsigned long long ull;

__device__ __align__(16) float g_wre[13824];     // rearranged weights (55.3 KB)

__device__ __forceinline__ ull pack2(float v) {
    unsigned r = __float_as_uint(v);
    ull d;
    asm("mov.b64 %0, {%1, %1};" : "=l"(d) : "r"(r));
    return d;
}

__device__ __forceinline__ void fma2(ull& a, ull b, ull c) {
    // packed dual-fp32 FMA (Blackwell f32x2 pipe)
    asm("fma.rn.f32x2 %0, %1, %2, %3;" : "=l"(a) : "l"(b), "l"(c), "l"(a));
}

__global__ void rearrange_w_kernel(const float* __restrict__ w) {
    int j = blockIdx.x * 256 + threadIdx.x;
    if (j < 13824) {
        int ic  = j / 864;
        int r   = j - ic * 864;
        int tap = r >> 5;
        int q   = r & 31;
        int g   = q >> 2;
        int s   = q & 3;
        int oc  = g + ((s & 1) << 4) + ((s >> 1) << 3);
        g_wre[j] = w[oc * 432 + ic * 27 + tap];
    }
}

__global__ __launch_bounds__(256, 3)
void conv_pool_lse_kernel(const float* __restrict__ x,
                          const float* __restrict__ bias,
                          float* __restrict__ out) {
    extern __shared__ char smem[];
    float* xs = reinterpret_cast<float*>(smem);                 // [16][4][10][18]

    const int tid = threadIdx.x;
    const int bz = blockIdx.z;
    const int b  = bz >> 4;
    const int od = bz & 15;
    const int OH0 = blockIdx.y * TOH;
    const int OW0 = blockIdx.x * TOW;

    // ---- x tile (halo + zero pad): xs[ic][xd][xh][xw], 4x10x18 per ic ----
    {
        const int d0 = od * 2 - 1;
        const int h0 = OH0 * 2 - 1;
        const int w0 = OW0 * 2 - 1;
        const float* xb = x + (long)b * (16 * 32 * 64 * 64);
        for (int i = tid; i < SMEM_X_FLOATS; i += 256) {
            int ic = i / 720;
            int r  = i - ic * 720;
            int xd = r / 180; r -= xd * 180;
            int xh = r / 18;
            int xw = r - xh * 18;
            int gd = d0 + xd, gh = h0 + xh, gw = w0 + xw;
            float v = 0.0f;
            if ((unsigned)gd < 32u && (unsigned)gh < 64u && (unsigned)gw < 64u)
                v = xb[((ic * 32 + gd) * 64 + gh) * 64 + gw];
            xs[i] = v;
        }
    }
    __syncthreads();

    // ---- main compute ----
    const int g   = tid & 7;           // oc group: channels g, g+16 (A) and g+8, g+24 (B)
    const int pos = tid >> 3;          // 0..31 pooled positions
    const int ph  = pos >> 3;          // 0..3
    const int pw  = pos & 7;           // 0..7
    const int ch  = ph * 2;            // conv-row base within tile (0..6)
    const int cw  = pw * 2;

    ull accA[2][2][2], accB[2][2][2];
#pragma unroll
    for (int i = 0; i < 2; ++i)
#pragma unroll
        for (int j = 0; j < 2; ++j)
#pragma unroll
            for (int k = 0; k < 2; ++k) { accA[i][j][k] = 0ull; accB[i][j][k] = 0ull; }

#pragma unroll 1
    for (int ic = 0; ic < 16; ++ic) {
        const float* xsl = xs + ic * 720;
        const ulonglong2* wl =
            reinterpret_cast<const ulonglong2*>(g_wre) + ic * (27 * 8) + g;

#pragma unroll
        for (int xd = 0; xd < 4; ++xd) {
            // 4x4 patch at depth slice xd; rows loaded as aligned float2 pairs,
            // then duplicated to f32x2 operands.
            ull xp[16];
#pragma unroll
            for (int row = 0; row < 4; ++row) {
                const float* rp = xsl + xd * 180 + (ch + row) * 18 + cw;
                float2 p0 = *reinterpret_cast<const float2*>(rp);
                float2 p1 = *reinterpret_cast<const float2*>(rp + 2);
                xp[row * 4 + 0] = pack2(p0.x);
                xp[row * 4 + 1] = pack2(p0.y);
                xp[row * 4 + 2] = pack2(p1.x);
                xp[row * 4 + 3] = pack2(p1.y);
            }

#pragma unroll
            for (int dd = 0; dd < 2; ++dd) {
                const int kd = xd - dd;
                if (kd < 0 || kd > 2) continue;
#pragma unroll
                for (int kh = 0; kh < 3; ++kh) {
                    // one LDG.128 per tap (128B line per warp, L1-resident)
                    ulonglong2 w0 = wl[(kd * 9 + kh * 3 + 0) * 8];
                    ulonglong2 w1 = wl[(kd * 9 + kh * 3 + 1) * 8];
                    ulonglong2 w2 = wl[(kd * 9 + kh * 3 + 2) * 8];
#pragma unroll
                    for (int kw = 0; kw < 3; ++kw) {
                        ulonglong2 wq = (kw == 0) ? w0 : (kw == 1) ? w1 : w2;
                        ull x00 = xp[(kh + 0) * 4 + kw + 0];
                        ull x01 = xp[(kh + 0) * 4 + kw + 1];
                        ull x10 = xp[(kh + 1) * 4 + kw + 0];
                        ull x11 = xp[(kh + 1) * 4 + kw + 1];
                        fma2(accA[dd][0][0], wq.x, x00);
                        fma2(accA[dd][0][1], wq.x, x01);
                        fma2(accA[dd][1][0], wq.x, x10);
                        fma2(accA[dd][1][1], wq.x, x11);
                        fma2(accB[dd][0][0], wq.y, x00);
                        fma2(accB[dd][0][1], wq.y, x01);
                        fma2(accB[dd][1][0], wq.y, x10);
                        fma2(accB[dd][1][1], wq.y, x11);
                    }
                }
            }
        }
    }

    // ---- maxpool over the 2x2x2 accumulators, + bias (4 channels/thread) ----
    float mA0 = -3.0e38f, mA1 = -3.0e38f, mB0 = -3.0e38f, mB1 = -3.0e38f;
#pragma unroll
    for (int i = 0; i < 2; ++i)
#pragma unroll
        for (int j = 0; j < 2; ++j)
#pragma unroll
            for (int k = 0; k < 2; ++k) {
                ull a = accA[i][j][k];
                ull c = accB[i][j][k];
                mA0 = fmaxf(mA0, __uint_as_float((unsigned)a));
                mA1 = fmaxf(mA1, __uint_as_float((unsigned)(a >> 32)));
                mB0 = fmaxf(mB0, __uint_as_float((unsigned)c));
                mB1 = fmaxf(mB1, __uint_as_float((unsigned)(c >> 32)));
            }
    mA0 += bias[g];
    mA1 += bias[g + 16];
    mB0 += bias[g + 8];
    mB1 += bias[g + 24];

    // ---- logsumexp over 32 channels (8 lanes x 4 channels each) + relu ----
    float m = fmaxf(fmaxf(mA0, mA1), fmaxf(mB0, mB1));
#pragma unroll
    for (int msk = 4; msk; msk >>= 1)
        m = fmaxf(m, __shfl_xor_sync(0xffffffffu, m, msk));
    float s = expf(mA0 - m) + expf(mA1 - m) + expf(mB0 - m) + expf(mB1 - m);
#pragma unroll
    for (int msk = 4; msk; msk >>= 1)
        s += __shfl_xor_sync(0xffffffffu, s, msk);

    if (g == 0) {
        float r = m + logf(s);
        out[((b * 16 + od) * 32 + (OH0 + ph)) * 32 + (OW0 + pw)] = fmaxf(r, 0.0f);
    }
}

extern "C" void kernel_launch(void* const* d_in, const int* in_sizes, int n_in,
                              void* d_out, int out_size) {
    (void)in_sizes; (void)n_in; (void)out_size;
    const float* x    = (const float*)d_in[0];
    const float* w    = (const float*)d_in[1];
    const float* bias = (const float*)d_in[2];
    float* out        = (float*)d_out;

    // 1) rearrange weights into the LDG-friendly interleaved layout
    rearrange_w_kernel<<<54, 256>>>(w);

    // 2) fused conv+pool+lse kernel (x tile in smem; weights via L1-cached LDG)
    dim3 grid(32 / TOW, 32 / TOH, 16 * 16);   // (4 ow tiles, 8 oh tiles, b*od)
    conv_pool_lse_kernel<<<grid, 256, SMEM_BYTES>>>(x, bias, out);
}

// round 15
// speedup vs baseline: 1.1656x; 1.1651x over previous
#include <cuda_runtime.h>
#include <cstdint>

// Fused: conv3d(16->32, k3, pad1) + bias + maxpool(2x2x2) + logsumexp(ch) + relu
// x: (16,16,32,64,64) f32, w: (32,16,3,3,3) f32, bias: (32) f32
// out: (16,1,16,32,32) f32
//
// R14: weights stay on the LDS path (R12 post-mortem: LDG weights => alu 34%,
// L2 50%) but smem holds only a 2-stage ring of per-ic weight slices (3.4KB
// each) filled by cp.async.cg from the rearranged global buffer. smem/block =
// 46KB (x) + 6.9KB (w) = 53KB -> 3 blocks/SM (6 warps/SMSP) for latency cover.
// Rolling 2-row x window keeps regs under the 85-reg occupancy-3 cap.

#define TOH 4
#define TOW 8
#define SMEM_X_FLOATS (16 * 4 * 10 * 18)          // 11520 floats = 46080 B
#define W_STAGE_U2    216                         // 27 taps x 8 groups, 16B each
#define SMEM_BYTES    (SMEM_X_FLOATS * 4 + 2 * W_STAGE_U2 * 16)   // 52992 B

typedef unsigned long long ull;

__device__ __align__(16) float g_wre[13824];      // rearranged weights (55.3 KB)

__device__ __forceinline__ ull pack2(float v) {
    unsigned r = __float_as_uint(v);
    ull d;
    asm("mov.b64 %0, {%1, %1};" : "=l"(d) : "r"(r));
    return d;
}

__device__ __forceinline__ void fma2(ull& a, ull b, ull c) {
    // packed dual-fp32 FMA (Blackwell f32x2 pipe)
    asm("fma.rn.f32x2 %0, %1, %2, %3;" : "=l"(a) : "l"(b), "l"(c), "l"(a));
}

__device__ __forceinline__ uint32_t smem_u32(const void* p) {
    uint32_t a;
    asm("{ .reg .u64 t; cvta.to.shared.u64 t, %1; cvt.u32.u64 %0, t; }"
        : "=r"(a) : "l"(p));
    return a;
}

__device__ __forceinline__ void cp16(uint32_t dst, const void* src) {
    asm volatile("cp.async.cg.shared.global [%0], [%1], 16;\n"
                 :: "r"(dst), "l"(src));
}

__global__ void rearrange_w_kernel(const float* __restrict__ w) {
    int j = blockIdx.x * 256 + threadIdx.x;
    if (j < 13824) {
        int ic  = j / 864;
        int r   = j - ic * 864;
        int tap = r >> 5;
        int q   = r & 31;
        int g   = q >> 2;
        int s   = q & 3;
        int oc  = g + ((s & 1) << 4) + ((s >> 1) << 3);
        g_wre[j] = w[oc * 432 + ic * 27 + tap];   // 16B entry per (ic,tap,g)
    }
}

__global__ __launch_bounds__(256, 3)
void conv_pool_lse_kernel(const float* __restrict__ x,
                          const float* __restrict__ bias,
                          float* __restrict__ out) {
    extern __shared__ char smem[];
    float* xs = reinterpret_cast<float*>(smem);                          // [16][4][10][18]
    ulonglong2* wring = reinterpret_cast<ulonglong2*>(smem + SMEM_X_FLOATS * 4); // [2][216]

    const int tid = threadIdx.x;
    const int bz = blockIdx.z;
    const int b  = bz >> 4;
    const int od = bz & 15;
    const int OH0 = blockIdx.y * TOH;
    const int OW0 = blockIdx.x * TOW;

    // ---- prefetch ic=0 weight slice into stage 0 (overlaps x-tile load) ----
    if (tid < W_STAGE_U2)
        cp16(smem_u32(wring + tid), reinterpret_cast<const char*>(g_wre) + tid * 16);
    asm volatile("cp.async.commit_group;\n");

    // ---- x tile (halo + zero pad): xs[ic][xd][xh][xw], 4x10x18 per ic ----
    {
        const int d0 = od * 2 - 1;
        const int h0 = OH0 * 2 - 1;
        const int w0 = OW0 * 2 - 1;
        const float* xb = x + (long)b * (16 * 32 * 64 * 64);
        for (int i = tid; i < SMEM_X_FLOATS; i += 256) {
            int ic = i / 720;
            int r  = i - ic * 720;
            int xd = r / 180; r -= xd * 180;
            int xh = r / 18;
            int xw = r - xh * 18;
            int gd = d0 + xd, gh = h0 + xh, gw = w0 + xw;
            float v = 0.0f;
            if ((unsigned)gd < 32u && (unsigned)gh < 64u && (unsigned)gw < 64u)
                v = xb[((ic * 32 + gd) * 64 + gh) * 64 + gw];
            xs[i] = v;
        }
    }

    // ---- main compute ----
    const int g   = tid & 7;           // oc group: channels g, g+16 (A) and g+8, g+24 (B)
    const int pos = tid >> 3;          // 0..31 pooled positions
    const int ph  = pos >> 3;          // 0..3
    const int pw  = pos & 7;           // 0..7
    const int ch  = ph * 2;            // conv-row base within tile (0..6)
    const int cw  = pw * 2;

    ull accA[2][2][2], accB[2][2][2];
#pragma unroll
    for (int i = 0; i < 2; ++i)
#pragma unroll
        for (int j = 0; j < 2; ++j)
#pragma unroll
            for (int k = 0; k < 2; ++k) { accA[i][j][k] = 0ull; accB[i][j][k] = 0ull; }

#pragma unroll 1
    for (int ic = 0; ic < 16; ++ic) {
        // prefetch next ic slice into the other stage, wait for current slice
        if (ic < 15) {
            if (tid < W_STAGE_U2)
                cp16(smem_u32(wring + ((ic + 1) & 1) * W_STAGE_U2 + tid),
                     reinterpret_cast<const char*>(g_wre + (ic + 1) * 864) + tid * 16);
            asm volatile("cp.async.commit_group;\n");
            asm volatile("cp.async.wait_group 1;\n");
        } else {
            asm volatile("cp.async.wait_group 0;\n");
        }
        __syncthreads();   // current weight stage + (first iter) x tile visible

        const float* xsl = xs + ic * 720;
        const ulonglong2* wb = wring + (ic & 1) * W_STAGE_U2 + g;

        auto loadrow = [&](ull* r, const float* p) {
            float2 a = *reinterpret_cast<const float2*>(p);
            float2 c = *reinterpret_cast<const float2*>(p + 2);
            r[0] = pack2(a.x); r[1] = pack2(a.y);
            r[2] = pack2(c.x); r[3] = pack2(c.y);
        };
        auto taps = [&](int xd, int kh, const ull* A, const ull* B) {
#pragma unroll
            for (int dd = 0; dd < 2; ++dd) {
                const int kd = xd - dd;
                if (kd < 0 || kd > 2) continue;
                ulonglong2 w0 = wb[(kd * 9 + kh * 3 + 0) * 8];
                ulonglong2 w1 = wb[(kd * 9 + kh * 3 + 1) * 8];
                ulonglong2 w2 = wb[(kd * 9 + kh * 3 + 2) * 8];
#pragma unroll
                for (int kw = 0; kw < 3; ++kw) {
                    ulonglong2 wq = (kw == 0) ? w0 : (kw == 1) ? w1 : w2;
                    fma2(accA[dd][0][0], wq.x, A[kw]);
                    fma2(accA[dd][0][1], wq.x, A[kw + 1]);
                    fma2(accA[dd][1][0], wq.x, B[kw]);
                    fma2(accA[dd][1][1], wq.x, B[kw + 1]);
                    fma2(accB[dd][0][0], wq.y, A[kw]);
                    fma2(accB[dd][0][1], wq.y, A[kw + 1]);
                    fma2(accB[dd][1][0], wq.y, B[kw]);
                    fma2(accB[dd][1][1], wq.y, B[kw + 1]);
                }
            }
        };

#pragma unroll
        for (int xd = 0; xd < 4; ++xd) {
            const float* rp = xsl + xd * 180 + ch * 18 + cw;
            // rolling 2-row window: row r feeds kh = r-1, r (j + kh = row)
            ull r0[4], r1[4], r2[4], r3[4];
            loadrow(r0, rp);
            loadrow(r1, rp + 18);
            taps(xd, 0, r0, r1);
            loadrow(r2, rp + 36);
            taps(xd, 1, r1, r2);
            loadrow(r3, rp + 54);
            taps(xd, 2, r2, r3);
        }
        __syncthreads();   // all warps done with this weight stage before overwrite
    }

    // ---- maxpool over the 2x2x2 accumulators, + bias (4 channels/thread) ----
    float mA0 = -3.0e38f, mA1 = -3.0e38f, mB0 = -3.0e38f, mB1 = -3.0e38f;
#pragma unroll
    for (int i = 0; i < 2; ++i)
#pragma unroll
        for (int j = 0; j < 2; ++j)
#pragma unroll
            for (int k = 0; k < 2; ++k) {
                ull a = accA[i][j][k];
                ull c = accB[i][j][k];
                mA0 = fmaxf(mA0, __uint_as_float((unsigned)a));
                mA1 = fmaxf(mA1, __uint_as_float((unsigned)(a >> 32)));
                mB0 = fmaxf(mB0, __uint_as_float((unsigned)c));
                mB1 = fmaxf(mB1, __uint_as_float((unsigned)(c >> 32)));
            }
    mA0 += bias[g];
    mA1 += bias[g + 16];
    mB0 += bias[g + 8];
    mB1 += bias[g + 24];

    // ---- logsumexp over 32 channels (8 lanes x 4 channels each) + relu ----
    float m = fmaxf(fmaxf(mA0, mA1), fmaxf(mB0, mB1));
#pragma unroll
    for (int msk = 4; msk; msk >>= 1)
        m = fmaxf(m, __shfl_xor_sync(0xffffffffu, m, msk));
    float s = expf(mA0 - m) + expf(mA1 - m) + expf(mB0 - m) + expf(mB1 - m);
#pragma unroll
    for (int msk = 4; msk; msk >>= 1)
        s += __shfl_xor_sync(0xffffffffu, s, msk);

    if (g == 0) {
        float r = m + logf(s);
        out[((b * 16 + od) * 32 + (OH0 + ph)) * 32 + (OW0 + pw)] = fmaxf(r, 0.0f);
    }
}

extern "C" void kernel_launch(void* const* d_in, const int* in_sizes, int n_in,
                              void* d_out, int out_size) {
    (void)in_sizes; (void)n_in; (void)out_size;
    const float* x    = (const float*)d_in[0];
    const float* w    = (const float*)d_in[1];
    const float* bias = (const float*)d_in[2];
    float* out        = (float*)d_out;

    // 1) rearrange weights into the cp.async-friendly interleaved layout
    rearrange_w_kernel<<<54, 256>>>(w);

    // 2) fused kernel: x tile in smem, per-ic weight slices streamed via cp.async
    (void)cudaFuncSetAttribute(conv_pool_lse_kernel,
                               cudaFuncAttributeMaxDynamicSharedMemorySize, SMEM_BYTES);
    dim3 grid(32 / TOW, 32 / TOH, 16 * 16);   // (4 ow tiles, 8 oh tiles, b*od)
    conv_pool_lse_kernel<<<grid, 256, SMEM_BYTES>>>(x, bias, out);
}